// round 1
// baseline (speedup 1.0000x reference)
#include <cuda_runtime.h>
#include <math.h>

#define NN 100000
#define NE 1600000
#define BB 2

// ---------------- constant weights ----------------
__constant__ float c_msg_w1[24*16];
__constant__ float c_msg_b1[16];
__constant__ float c_msg_w2[16*24];
__constant__ float c_msg_b2[24];
__constant__ float c_att_w1[8*16];
__constant__ float c_att_b1[16];
__constant__ float c_att_w2[16*32];
__constant__ float c_att_b2[32];
__constant__ float c_upd_w1[24*16];
__constant__ float c_upd_b1[16];
__constant__ float c_upd_w2[16*8];
__constant__ float c_upd_b2[8];

// ---------------- scratch (device globals; no allocation) ----------------
// per-node source-side record: [Pa(16), a_query(8), a_key(8)]  = 8 float4
// per-node target-side record: [Pb(16), b_key(8),  b_query(8)] = 8 float4
__device__ float4 g_src[(size_t)BB*NN*8];
__device__ float4 g_tgt[(size_t)BB*NN*8];
__device__ float4 g_numA[(size_t)BB*NN*2];
__device__ float4 g_numB[(size_t)BB*NN*2];
__device__ float  g_denA[(size_t)BB*NN];
__device__ float  g_denB[(size_t)BB*NN];

__device__ __forceinline__ float softclamp(float v) {
    // 1e6 * tanh(v * 1e-6); for |t| <= 1e-4 tanh(t)==t within fp32 eps
    float t = v * 1e-6f;
    if (fabsf(t) > 1e-4f) t = tanhf(t);
    return 1e6f * t;
}

// ================= kernel A: per-node precompute + accumulator zeroing =================
__global__ __launch_bounds__(256) void node_pre(const float* __restrict__ nodes) {
    int n = blockIdx.x * blockDim.x + threadIdx.x;
    if (n >= NN) return;
    size_t idx = (size_t)blockIdx.y * NN + n;

    float x[8];
    float4 v0 = __ldg((const float4*)(nodes + idx*8));
    float4 v1 = __ldg((const float4*)(nodes + idx*8) + 1);
    x[0]=v0.x; x[1]=v0.y; x[2]=v0.z; x[3]=v0.w;
    x[4]=v1.x; x[5]=v1.y; x[6]=v1.z; x[7]=v1.w;

    float pa[16], pb[16], h[16];
#pragma unroll
    for (int j = 0; j < 16; j++) { pa[j] = c_msg_b1[j]; pb[j] = 0.f; h[j] = c_att_b1[j]; }
#pragma unroll
    for (int i = 0; i < 8; i++) {
#pragma unroll
        for (int j = 0; j < 16; j++) {
            pa[j] = fmaf(x[i], c_msg_w1[i*16 + j],     pa[j]);
            pb[j] = fmaf(x[i], c_msg_w1[(8+i)*16 + j], pb[j]);
            h[j]  = fmaf(x[i], c_att_w1[i*16 + j],     h[j]);
        }
    }
#pragma unroll
    for (int j = 0; j < 16; j++) h[j] = tanhf(h[j]);

    float att[32];
#pragma unroll
    for (int j = 0; j < 32; j++) att[j] = c_att_b2[j];
#pragma unroll
    for (int i = 0; i < 16; i++)
#pragma unroll
        for (int j = 0; j < 32; j++) att[j] = fmaf(h[i], c_att_w2[i*32 + j], att[j]);

    // att layout (jnp.split order): a_key[0:8] a_query[8:16] b_key[16:24] b_query[24:32]
    float4* sr = g_src + idx*8;
    sr[0] = make_float4(pa[0],  pa[1],  pa[2],  pa[3]);
    sr[1] = make_float4(pa[4],  pa[5],  pa[6],  pa[7]);
    sr[2] = make_float4(pa[8],  pa[9],  pa[10], pa[11]);
    sr[3] = make_float4(pa[12], pa[13], pa[14], pa[15]);
    sr[4] = make_float4(att[8],  att[9],  att[10], att[11]);   // a_query
    sr[5] = make_float4(att[12], att[13], att[14], att[15]);
    sr[6] = make_float4(att[0],  att[1],  att[2],  att[3]);    // a_key
    sr[7] = make_float4(att[4],  att[5],  att[6],  att[7]);

    float4* tr = g_tgt + idx*8;
    tr[0] = make_float4(pb[0],  pb[1],  pb[2],  pb[3]);
    tr[1] = make_float4(pb[4],  pb[5],  pb[6],  pb[7]);
    tr[2] = make_float4(pb[8],  pb[9],  pb[10], pb[11]);
    tr[3] = make_float4(pb[12], pb[13], pb[14], pb[15]);
    tr[4] = make_float4(att[16], att[17], att[18], att[19]);   // b_key
    tr[5] = make_float4(att[20], att[21], att[22], att[23]);
    tr[6] = make_float4(att[24], att[25], att[26], att[27]);   // b_query
    tr[7] = make_float4(att[28], att[29], att[30], att[31]);

    g_denA[idx] = 0.f;
    g_denB[idx] = 0.f;
    float4 z = make_float4(0.f, 0.f, 0.f, 0.f);
    g_numA[idx*2]   = z; g_numA[idx*2+1] = z;
    g_numB[idx*2]   = z; g_numB[idx*2+1] = z;
}

// ================= kernel B: single fused edge pass =================
__global__ __launch_bounds__(256) void edge_pass(const float* __restrict__ edges,
                                                 const int* __restrict__ srcs,
                                                 const int* __restrict__ tgts,
                                                 float* __restrict__ out_edges) {
    int e = blockIdx.x * blockDim.x + threadIdx.x;
    if (e >= NE) return;
    int b = blockIdx.y;
    int s = __ldg(srcs + e);
    int t = __ldg(tgts + e);

    const float4* sr = g_src + ((size_t)b*NN + s)*8;
    const float4* tr = g_tgt + ((size_t)b*NN + t)*8;

    size_t eoff = ((size_t)b*NE + e)*8;
    float4 e0 = __ldg((const float4*)(edges + eoff));
    float4 e1 = __ldg((const float4*)(edges + eoff) + 1);
    float x[8] = {e0.x, e0.y, e0.z, e0.w, e1.x, e1.y, e1.z, e1.w};

    float h[16];
    {
        float4 a0 = sr[0], a1 = sr[1], a2 = sr[2], a3 = sr[3];
        float4 c0 = tr[0], c1 = tr[1], c2 = tr[2], c3 = tr[3];
        h[0]=a0.x+c0.x;  h[1]=a0.y+c0.y;  h[2]=a0.z+c0.z;  h[3]=a0.w+c0.w;
        h[4]=a1.x+c1.x;  h[5]=a1.y+c1.y;  h[6]=a1.z+c1.z;  h[7]=a1.w+c1.w;
        h[8]=a2.x+c2.x;  h[9]=a2.y+c2.y;  h[10]=a2.z+c2.z; h[11]=a2.w+c2.w;
        h[12]=a3.x+c3.x; h[13]=a3.y+c3.y; h[14]=a3.z+c3.z; h[15]=a3.w+c3.w;
    }
#pragma unroll
    for (int i = 0; i < 8; i++)
#pragma unroll
        for (int j = 0; j < 16; j++)
            h[j] = fmaf(x[i], c_msg_w1[(16+i)*16 + j], h[j]);
#pragma unroll
    for (int j = 0; j < 16; j++) h[j] = tanhf(h[j]);

    float y[24];
#pragma unroll
    for (int k = 0; k < 24; k++) y[k] = c_msg_b2[k];
#pragma unroll
    for (int i = 0; i < 16; i++)
#pragma unroll
        for (int k = 0; k < 24; k++) y[k] = fmaf(h[i], c_msg_w2[i*24 + k], y[k]);

    // new_edges = soft_clamp(edges + m_ab)
    float4 o0 = make_float4(softclamp(x[0]+y[16]), softclamp(x[1]+y[17]),
                            softclamp(x[2]+y[18]), softclamp(x[3]+y[19]));
    float4 o1 = make_float4(softclamp(x[4]+y[20]), softclamp(x[5]+y[21]),
                            softclamp(x[6]+y[22]), softclamp(x[7]+y[23]));
    ((float4*)(out_edges + eoff))[0] = o0;
    ((float4*)(out_edges + eoff))[1] = o1;

    // logits: la = a_query[s] . b_key[t], lb = b_query[t] . a_key[s]
    float4 q0 = sr[4], q1 = sr[5], ak0 = sr[6], ak1 = sr[7];
    float4 bk0 = tr[4], bk1 = tr[5], bq0 = tr[6], bq1 = tr[7];
    float la = q0.x*bk0.x + q0.y*bk0.y + q0.z*bk0.z + q0.w*bk0.w
             + q1.x*bk1.x + q1.y*bk1.y + q1.z*bk1.z + q1.w*bk1.w;
    float lb = bq0.x*ak0.x + bq0.y*ak0.y + bq0.z*ak0.z + bq0.w*ak0.w
             + bq1.x*ak1.x + bq1.y*ak1.y + bq1.z*ak1.z + bq1.w*ak1.w;
    const float scale = 0.3535533905932738f; // 1/sqrt(8)
    float exa = __expf(la * scale);
    float exb = __expf(lb * scale);

    size_t si = (size_t)b*NN + s;
    size_t ti = (size_t)b*NN + t;
    atomicAdd(&g_denA[si], exa);
    atomicAdd(&g_denB[ti], exb);
    atomicAdd(&g_numA[si*2],   make_float4(exa*y[0], exa*y[1], exa*y[2],  exa*y[3]));
    atomicAdd(&g_numA[si*2+1], make_float4(exa*y[4], exa*y[5], exa*y[6],  exa*y[7]));
    atomicAdd(&g_numB[ti*2],   make_float4(exb*y[8], exb*y[9], exb*y[10], exb*y[11]));
    atomicAdd(&g_numB[ti*2+1], make_float4(exb*y[12],exb*y[13],exb*y[14], exb*y[15]));
}

// ================= kernel C: node update =================
__global__ __launch_bounds__(256) void node_post(const float* __restrict__ nodes,
                                                 float* __restrict__ out_nodes) {
    int n = blockIdx.x * blockDim.x + threadIdx.x;
    if (n >= NN) return;
    size_t idx = (size_t)blockIdx.y * NN + n;

    float x[24];
    float4 v0 = __ldg((const float4*)(nodes + idx*8));
    float4 v1 = __ldg((const float4*)(nodes + idx*8) + 1);
    x[0]=v0.x; x[1]=v0.y; x[2]=v0.z; x[3]=v0.w;
    x[4]=v1.x; x[5]=v1.y; x[6]=v1.z; x[7]=v1.w;

    float ia = 1.f / (g_denA[idx] + 1e-10f);
    float4 na0 = g_numA[idx*2], na1 = g_numA[idx*2+1];
    x[8]=na0.x*ia;  x[9]=na0.y*ia;  x[10]=na0.z*ia; x[11]=na0.w*ia;
    x[12]=na1.x*ia; x[13]=na1.y*ia; x[14]=na1.z*ia; x[15]=na1.w*ia;

    float ib = 1.f / (g_denB[idx] + 1e-10f);
    float4 nb0 = g_numB[idx*2], nb1 = g_numB[idx*2+1];
    x[16]=nb0.x*ib; x[17]=nb0.y*ib; x[18]=nb0.z*ib; x[19]=nb0.w*ib;
    x[20]=nb1.x*ib; x[21]=nb1.y*ib; x[22]=nb1.z*ib; x[23]=nb1.w*ib;

    float h[16];
#pragma unroll
    for (int j = 0; j < 16; j++) h[j] = c_upd_b1[j];
#pragma unroll
    for (int i = 0; i < 24; i++)
#pragma unroll
        for (int j = 0; j < 16; j++) h[j] = fmaf(x[i], c_upd_w1[i*16 + j], h[j]);
#pragma unroll
    for (int j = 0; j < 16; j++) h[j] = tanhf(h[j]);

    float u[8];
#pragma unroll
    for (int j = 0; j < 8; j++) u[j] = c_upd_b2[j];
#pragma unroll
    for (int i = 0; i < 16; i++)
#pragma unroll
        for (int j = 0; j < 8; j++) u[j] = fmaf(h[i], c_upd_w2[i*8 + j], u[j]);

    float4 r0 = make_float4(softclamp(x[0]+u[0]), softclamp(x[1]+u[1]),
                            softclamp(x[2]+u[2]), softclamp(x[3]+u[3]));
    float4 r1 = make_float4(softclamp(x[4]+u[4]), softclamp(x[5]+u[5]),
                            softclamp(x[6]+u[6]), softclamp(x[7]+u[7]));
    ((float4*)(out_nodes + idx*8))[0] = r0;
    ((float4*)(out_nodes + idx*8))[1] = r1;
}

extern "C" void kernel_launch(void* const* d_in, const int* in_sizes, int n_in,
                              void* d_out, int out_size) {
    (void)in_sizes; (void)n_in; (void)out_size;
    const float* nodes = (const float*)d_in[0];
    const float* edges = (const float*)d_in[1];
    const int*   srcs  = (const int*)d_in[14];
    const int*   tgts  = (const int*)d_in[15];

    cudaMemcpyToSymbolAsync(c_msg_w1, d_in[2],  24*16*sizeof(float), 0, cudaMemcpyDeviceToDevice, 0);
    cudaMemcpyToSymbolAsync(c_msg_b1, d_in[3],  16*sizeof(float),    0, cudaMemcpyDeviceToDevice, 0);
    cudaMemcpyToSymbolAsync(c_msg_w2, d_in[4],  16*24*sizeof(float), 0, cudaMemcpyDeviceToDevice, 0);
    cudaMemcpyToSymbolAsync(c_msg_b2, d_in[5],  24*sizeof(float),    0, cudaMemcpyDeviceToDevice, 0);
    cudaMemcpyToSymbolAsync(c_att_w1, d_in[6],  8*16*sizeof(float),  0, cudaMemcpyDeviceToDevice, 0);
    cudaMemcpyToSymbolAsync(c_att_b1, d_in[7],  16*sizeof(float),    0, cudaMemcpyDeviceToDevice, 0);
    cudaMemcpyToSymbolAsync(c_att_w2, d_in[8],  16*32*sizeof(float), 0, cudaMemcpyDeviceToDevice, 0);
    cudaMemcpyToSymbolAsync(c_att_b2, d_in[9],  32*sizeof(float),    0, cudaMemcpyDeviceToDevice, 0);
    cudaMemcpyToSymbolAsync(c_upd_w1, d_in[10], 24*16*sizeof(float), 0, cudaMemcpyDeviceToDevice, 0);
    cudaMemcpyToSymbolAsync(c_upd_b1, d_in[11], 16*sizeof(float),    0, cudaMemcpyDeviceToDevice, 0);
    cudaMemcpyToSymbolAsync(c_upd_w2, d_in[12], 16*8*sizeof(float),  0, cudaMemcpyDeviceToDevice, 0);
    cudaMemcpyToSymbolAsync(c_upd_b2, d_in[13], 8*sizeof(float),     0, cudaMemcpyDeviceToDevice, 0);

    float* out_nodes = (float*)d_out;
    float* out_edges = out_nodes + (size_t)BB*NN*8;

    dim3 gN((NN + 255)/256, BB);
    dim3 gE((NE + 255)/256, BB);
    node_pre<<<gN, 256>>>(nodes);
    edge_pass<<<gE, 256>>>(edges, srcs, tgts, out_edges);
    node_post<<<gN, 256>>>(nodes, out_nodes);
}